// round 14
// baseline (speedup 1.0000x reference)
#include <cuda_runtime.h>

#define Hdim 1024
#define H2   512
#define Bb   4
#define Ss   2048
#define NGRP 2       // independent sync groups (2 batches each)
#define GBLK 48      // blocks per group (32 rec + 16 tau)
#define NBLK (NGRP * GBLK)
#define RPB  32      // weight rows per block
#define NT   256     // 8 warps
#define DTc  0.1f
#define SCALEc 0.01f

// ---------------- device scratch (static, no allocation) ----------------
__device__ float    g_fz[2 * NGRP * 2 * Hdim];   // [par][grp][b_local][H]
__device__ float    g_part[2 * NGRP * 8 * GBLK]; // [par][grp][scalar][block]
__device__ float    g_pretau[(size_t)Bb * Ss * H2];
__device__ unsigned g_bars[NGRP * 64];           // per group: counter @+0, flag @+32 (128B apart)

// ---------------- reset (runs every launch; graph-replay safe) ----------
__global__ void reset_kernel() {
    int i = threadIdx.x;
    if (i < NGRP * 64) g_bars[i] = 0u;
}

// ---------------- pre-tau GEMM (unchanged) -------------------------------
__global__ void pretau_gemm(const float* __restrict__ X,
                            const float* __restrict__ tw1,
                            const float* __restrict__ b1) {
    __shared__ float As[16][128];
    __shared__ float Bs[16][64];
    const int tx = threadIdx.x;
    const int row0 = blockIdx.y * 128;
    const int col0 = blockIdx.x * 64;
    const int tr = tx >> 4, tc = tx & 15;
    float acc[8][4];
#pragma unroll
    for (int i = 0; i < 8; i++)
#pragma unroll
        for (int j = 0; j < 4; j++) acc[i][j] = 0.f;

    for (int k0 = 0; k0 < Hdim; k0 += 16) {
#pragma unroll
        for (int l = 0; l < 2; l++) {
            int f = tx + l * 256;
            int r = f >> 2, c4 = (f & 3) << 2;
            float4 v = *reinterpret_cast<const float4*>(X + (size_t)(row0 + r) * Hdim + k0 + c4);
            As[c4 + 0][r] = v.x; As[c4 + 1][r] = v.y; As[c4 + 2][r] = v.z; As[c4 + 3][r] = v.w;
        }
        {
            int r = tx >> 4, c4 = (tx & 15) << 2;
            *reinterpret_cast<float4*>(&Bs[r][c4]) =
                *reinterpret_cast<const float4*>(tw1 + (size_t)(k0 + r) * H2 + col0 + c4);
        }
        __syncthreads();
#pragma unroll
        for (int k = 0; k < 16; k++) {
            float a[8], bb[4];
#pragma unroll
            for (int i = 0; i < 8; i++) a[i] = As[k][tr * 8 + i];
#pragma unroll
            for (int j = 0; j < 4; j++) bb[j] = Bs[k][tc * 4 + j];
#pragma unroll
            for (int i = 0; i < 8; i++)
#pragma unroll
                for (int j = 0; j < 4; j++) acc[i][j] += a[i] * bb[j];
        }
        __syncthreads();
    }
    float4 bv = *reinterpret_cast<const float4*>(b1 + col0 + tc * 4);
#pragma unroll
    for (int i = 0; i < 8; i++) {
        float4 o = make_float4(acc[i][0] + bv.x, acc[i][1] + bv.y,
                               acc[i][2] + bv.z, acc[i][3] + bv.w);
        *reinterpret_cast<float4*>(&g_pretau[(size_t)(row0 + tr * 8 + i) * H2 + col0 + tc * 4]) = o;
    }
}

// ---------------- conv pass: out = 0.99 * shortconv(x) (unchanged) -------
__global__ void conv_kernel(const float* __restrict__ X,
                            const float* __restrict__ cw,
                            float* __restrict__ out) {
    int idx = blockIdx.x * blockDim.x + threadIdx.x;
    if (idx >= Bb * Ss * (Hdim / 4)) return;
    int t = (idx >> 8) & (Ss - 1);
    int b = idx >> 19;
    int j = (idx & 255) << 2;
    float w[4][4];
#pragma unroll
    for (int r = 0; r < 4; r++) {
        float4 wr = *reinterpret_cast<const float4*>(cw + (j + r) * 4);
        w[r][0] = wr.x; w[r][1] = wr.y; w[r][2] = wr.z; w[r][3] = wr.w;
    }
    const float* xb = X + (size_t)b * Ss * Hdim;
    float4 acc = make_float4(0.f, 0.f, 0.f, 0.f);
#pragma unroll
    for (int k = 0; k < 4; k++) {
        int tt = t - 3 + k;
        if (tt >= 0) {
            float4 xv = *reinterpret_cast<const float4*>(xb + (size_t)tt * Hdim + j);
            acc.x += w[0][k] * xv.x; acc.y += w[1][k] * xv.y;
            acc.z += w[2][k] * xv.z; acc.w += w[3][k] * xv.w;
        }
    }
    acc.x *= (1.f - SCALEc); acc.y *= (1.f - SCALEc);
    acc.z *= (1.f - SCALEc); acc.w *= (1.f - SCALEc);
    *reinterpret_cast<float4*>(out + (size_t)idx * 4) = acc;
}

// ---------------- persistent liquid recurrence ---------------------------
// 2 independent 48-block groups (2 batches each). One group barrier per
// step: arrivals on a dedicated counter line (atomics only, never polled);
// the LAST arriver announces on a separate flag line that others poll.
// All asm forms are verbatim from previously passing builds.
__global__ void __launch_bounds__(NT, 1)
liquid_kernel(const float* __restrict__ X,
              const float* __restrict__ Wrec,
              const float* __restrict__ tw1,
              const float* __restrict__ tw2,
              const float* __restrict__ tb2p,
              const float* __restrict__ lngp,
              const float* __restrict__ lnbp,
              float* __restrict__ out) {
    extern __shared__ float sm[];
    float* w_s  = sm;                       // 32768
    float* h_s  = w_s + RPB * Hdim;         // 2048  (2 local batches)
    float* lng  = h_s + 2 * Hdim;           // 1024
    float* lnb  = lng + Hdim;               // 1024
    float* red  = lnb + Hdim;               // 128 : [p][row0..31][b0..1]
    float* red2 = red + 128;                // 32
    float* xpre = red2 + 32;                // 64
    float* w2s  = xpre + 64;                // 32
    float* shs  = w2s + 32;                 // 2
    float* shhs = shs + 2;                  // 2
    float* scal = shhs + 2;                 // 8 : a[2] oma[2] mu[2] rstd[2]

    const int tid  = threadIdx.x;
    const int warp = tid >> 5, lane = tid & 31;
    const int gid  = blockIdx.x / GBLK;      // sync group (batch pair)
    const int lblk = blockIdx.x % GBLK;      // block within group
    const int r0   = lblk * RPB;
    const bool isrec = (r0 < Hdim);
    const bool owner = isrec && ((unsigned)(tid - (r0 >> 2)) < 8u);
    const float tb2 = *tb2p;
    unsigned* cntp  = &g_bars[gid * 64];
    unsigned* flagp = &g_bars[gid * 64 + 32];
    float* fzg  = g_fz + gid * (2 * Hdim);
    float* parg = g_part + gid * (8 * GBLK);

    // ---- one-time: weights / ln params / zero h ----
    if (isrec) {
        for (int idx = tid; idx < RPB * (Hdim / 4); idx += NT) {
            int rl = idx >> 8; int i4 = (idx & 255) << 2;
            *reinterpret_cast<float4*>(&w_s[rl * Hdim + i4]) =
                *reinterpret_cast<const float4*>(Wrec + (size_t)(r0 + rl) * Hdim + i4);
        }
    } else {
        int m0 = r0 - Hdim;
        for (int idx = tid; idx < RPB * Hdim; idx += NT) {
            int rl = idx & (RPB - 1); int i = idx >> 5;  // transpose of tau_w1 bottom half
            w_s[rl * Hdim + i] = tw1[(size_t)(Hdim + i) * H2 + m0 + rl];
        }
        if (tid < RPB) w2s[tid] = tw2[r0 - Hdim + tid];
    }
    for (int i = tid; i < Hdim; i += NT) { lng[i] = lngp[i]; lnb[i] = lnbp[i]; }
    for (int i = tid; i < 2 * Hdim / 4; i += NT)
        *reinterpret_cast<float4*>(&h_s[i * 4]) = make_float4(0.f, 0.f, 0.f, 0.f);
    if (tid < 2) { shs[tid] = 0.f; shhs[tid] = 0.f; }
    __syncthreads();

    const int g  = warp >> 1;      // row group 0..3 (8 rows each)
    const int p  = warp & 1;       // column half
    const int rb = g * 8;

    for (int t = 0; t < Ss; t++) {
        const int par = t & 1;
        float* fz = fzg + par * (NGRP * 2 * Hdim);
        float* P  = parg + par * (NGRP * 8 * GBLK);

        // ---- prefetch x_t / pretau + conv(out) values (hidden under matvec) ----
        if (tid < 64) {
            int b = tid >> 5, rl = tid & 31;
            int gb = gid * 2 + b;
            if (isrec) xpre[tid] = X[(size_t)(gb * Ss + t) * Hdim + r0 + rl];
            else       xpre[tid] = g_pretau[(size_t)(gb * Ss + t) * H2 + (r0 - Hdim) + rl];
        }
        float4 outv[2];
        if (owner) {
#pragma unroll
            for (int b = 0; b < 2; b++)
                outv[b] = *reinterpret_cast<const float4*>(
                              &out[(size_t)((gid * 2 + b) * Ss + t) * Hdim + tid * 4]);
        }

        // ---- Phase A: matvec. warp-pair = 8 rows x 2 batches, column-split ----
        float av[8][2];
#pragma unroll
        for (int r = 0; r < 8; r++) { av[r][0] = 0.f; av[r][1] = 0.f; }
#pragma unroll
        for (int c = 0; c < 4; c++) {
            int base = p * 512 + c * 128 + lane * 4;
            float4 h0 = *reinterpret_cast<const float4*>(&h_s[base]);
            float4 h1 = *reinterpret_cast<const float4*>(&h_s[Hdim + base]);
#pragma unroll
            for (int r = 0; r < 8; r++) {
                float4 wv = *reinterpret_cast<const float4*>(&w_s[(rb + r) * Hdim + base]);
                av[r][0] += wv.x * h0.x + wv.y * h0.y + wv.z * h0.z + wv.w * h0.w;
                av[r][1] += wv.x * h1.x + wv.y * h1.y + wv.z * h1.z + wv.w * h1.w;
            }
        }
#pragma unroll
        for (int r = 0; r < 8; r++)
#pragma unroll
            for (int b = 0; b < 2; b++) {
                float v = av[r][b];
#pragma unroll
                for (int off = 16; off > 0; off >>= 1) v += __shfl_down_sync(0xffffffffu, v, off);
                if (lane == 0) red[p * 64 + (rb + r) * 2 + b] = v;
            }
        __syncthreads();

        // ---- f/z + per-block scalar partial stores (warp = batch) ----
        if (tid < 64) {
            int b = warp, rl = lane;
            float d = red[rl * 2 + b] + red[64 + rl * 2 + b];
            if (isrec) {
                float f = tanhf(xpre[tid] + d);
                fz[b * Hdim + r0 + rl] = f;
                float hv = h_s[b * Hdim + r0 + rl];
                float pf = f, pff = f * f, phf = hv * f;
#pragma unroll
                for (int off = 16; off > 0; off >>= 1) {
                    pf  += __shfl_down_sync(0xffffffffu, pf,  off);
                    pff += __shfl_down_sync(0xffffffffu, pff, off);
                    phf += __shfl_down_sync(0xffffffffu, phf, off);
                }
                if (rl == 0) {
                    P[(b * 4 + 1) * GBLK + lblk] = pf;
                    P[(b * 4 + 2) * GBLK + lblk] = pff;
                    P[(b * 4 + 3) * GBLK + lblk] = phf;
                }
            } else {
                float z = tanhf(xpre[tid] + d);
                float pz = z * w2s[rl];
#pragma unroll
                for (int off = 16; off > 0; off >>= 1)
                    pz += __shfl_down_sync(0xffffffffu, pz, off);
                if (rl == 0) P[(b * 4 + 0) * GBLK + lblk] = pz;
            }
        }
        __syncthreads();   // CTA-scope happens-before for all STGs above

        // ---- announcer-flag group barrier (proven asm forms only) ----
        if (tid == 0) {
            unsigned target = (unsigned)(t + 1) * GBLK;
            unsigned old;
            asm volatile("atom.add.release.gpu.global.u32 %0, [%1], 1;"
                         : "=r"(old) : "l"(cntp) : "memory");
            if (old == target - 1u) {
                unsigned tmp;
                asm volatile("ld.acquire.gpu.u32 %0, [%1];"
                             : "=r"(tmp) : "l"(cntp) : "memory");
                asm volatile("st.release.gpu.u32 [%0], %1;"
                             :: "l"(flagp), "r"((unsigned)(t + 1)) : "memory");
            } else {
                unsigned v;
                do { asm volatile("ld.acquire.gpu.u32 %0, [%1];"
                                  : "=r"(v) : "l"(flagp) : "memory"); }
                while (v < (unsigned)(t + 1));
            }
        }
        __syncthreads();

        // ---- Phase B: prefetch f into registers FIRST ----
        float4 f4r[2];
#pragma unroll
        for (int b = 0; b < 2; b++)
            f4r[b] = __ldcg(reinterpret_cast<const float4*>(&fz[b * Hdim + tid * 4]));

        // ---- cross-block scalar reduction: warp b handles batch b ----
        if (warp < 2) {
            const int b = warp;
            float z   = (lane < GBLK - 32)
                          ? __ldcg(&P[(b * 4 + 0) * GBLK + 32 + lane]) : 0.f;   // 16 tau blocks
            float sf  = __ldcg(&P[(b * 4 + 1) * GBLK + lane]);                  // 32 rec blocks
            float sff = __ldcg(&P[(b * 4 + 2) * GBLK + lane]);
            float shf = __ldcg(&P[(b * 4 + 3) * GBLK + lane]);
#pragma unroll
            for (int off = 16; off > 0; off >>= 1) {
                z   += __shfl_down_sync(0xffffffffu, z,   off);
                sf  += __shfl_down_sync(0xffffffffu, sf,  off);
                sff += __shfl_down_sync(0xffffffffu, sff, off);
                shf += __shfl_down_sync(0xffffffffu, shf, off);
            }
            if (lane == 0) {
                float sig = 1.f / (1.f + expf(-(z + tb2)));
                float tau = 1.f + 4.f * sig;
                float a = DTc / tau, oma = 1.f - a;
                float mu  = (oma * shs[b] + a * sf) * (1.f / (float)Hdim);
                float sy2 = oma * oma * shhs[b] + 2.f * a * oma * shf + a * a * sff;
                float var = sy2 * (1.f / (float)Hdim) - mu * mu;
                scal[b] = a; scal[2 + b] = oma; scal[4 + b] = mu;
                scal[6 + b] = rsqrtf(var + 1e-5f);
            }
        }
        __syncthreads();

        // ---- local h update (2 batches) + fused out write + Sh/Shh ----
        {
            const int j4 = tid * 4;
            float4 g4 = *reinterpret_cast<const float4*>(&lng[j4]);
            float4 b4 = *reinterpret_cast<const float4*>(&lnb[j4]);
            float psh[2], pshh[2];
#pragma unroll
            for (int b = 0; b < 2; b++) {
                float a = scal[b], oma = scal[2 + b], mu = scal[4 + b], rs = scal[6 + b];
                float4 f4 = f4r[b];
                float4 h4 = *reinterpret_cast<const float4*>(&h_s[b * Hdim + j4]);
                float4 hn;
                hn.x = (oma * h4.x + a * f4.x - mu) * rs * g4.x + b4.x;
                hn.y = (oma * h4.y + a * f4.y - mu) * rs * g4.y + b4.y;
                hn.z = (oma * h4.z + a * f4.z - mu) * rs * g4.z + b4.z;
                hn.w = (oma * h4.w + a * f4.w - mu) * rs * g4.w + b4.w;
                *reinterpret_cast<float4*>(&h_s[b * Hdim + j4]) = hn;
                if (owner) {
                    float4 o4;
                    o4.x = outv[b].x + SCALEc * hn.x;
                    o4.y = outv[b].y + SCALEc * hn.y;
                    o4.z = outv[b].z + SCALEc * hn.z;
                    o4.w = outv[b].w + SCALEc * hn.w;
                    *reinterpret_cast<float4*>(
                        &out[(size_t)((gid * 2 + b) * Ss + t) * Hdim + j4]) = o4;
                }
                psh[b]  = hn.x + hn.y + hn.z + hn.w;
                pshh[b] = hn.x * hn.x + hn.y * hn.y + hn.z * hn.z + hn.w * hn.w;
            }
#pragma unroll
            for (int b = 0; b < 2; b++) {
                float v1 = psh[b], v2 = pshh[b];
#pragma unroll
                for (int off = 16; off > 0; off >>= 1) {
                    v1 += __shfl_down_sync(0xffffffffu, v1, off);
                    v2 += __shfl_down_sync(0xffffffffu, v2, off);
                }
                if (lane == 0) { red2[warp * 4 + b * 2] = v1; red2[warp * 4 + b * 2 + 1] = v2; }
            }
        }
        __syncthreads();
        if (tid < 4) {
            int b = tid >> 1, k = tid & 1;
            float s = 0.f;
#pragma unroll
            for (int w = 0; w < 8; w++) s += red2[w * 4 + tid];
            if (k == 0) shs[b] = s; else shhs[b] = s;
        }
        // no trailing sync: shs/shhs consumers are past next step's barriers
    }
}

// ---------------- launch --------------------------------------------------
extern "C" void kernel_launch(void* const* d_in, const int* in_sizes, int n_in,
                              void* d_out, int out_size) {
    const float* X   = (const float*)d_in[0];
    const float* cw  = (const float*)d_in[1];
    const float* Wr  = (const float*)d_in[2];
    const float* tw1 = (const float*)d_in[3];
    const float* tb1 = (const float*)d_in[4];
    const float* tw2 = (const float*)d_in[5];
    const float* tb2 = (const float*)d_in[6];
    const float* lg  = (const float*)d_in[7];
    const float* lb  = (const float*)d_in[8];
    float* out = (float*)d_out;

    const int smem_bytes = (RPB * Hdim + 2 * Hdim + Hdim + Hdim +
                            128 + 32 + 64 + 32 + 2 + 2 + 8) * 4;
    cudaFuncSetAttribute(liquid_kernel, cudaFuncAttributeMaxDynamicSharedMemorySize, smem_bytes);

    reset_kernel<<<1, 128>>>();

    dim3 ggrid(H2 / 64, (Bb * Ss) / 128);
    pretau_gemm<<<ggrid, 256>>>(X, tw1, tb1);

    conv_kernel<<<(Bb * Ss * (Hdim / 4)) / 256, 256>>>(X, cw, out);

    liquid_kernel<<<NBLK, NT, smem_bytes>>>(X, Wr, tw1, tw2, tb2, lg, lb, out);
}

// round 15
// speedup vs baseline: 1.1592x; 1.1592x over previous
#include <cuda_runtime.h>

#define Hdim 1024
#define H2   512
#define Bb   4
#define Ss   2048
#define NGRP 2       // independent sync groups (2 batches each)
#define GBLK 48      // blocks per group (32 rec + 16 tau)
#define NBLK (NGRP * GBLK)
#define RPB  32      // weight rows per block
#define NT   256     // 8 warps
#define DTc  0.1f
#define SCALEc 0.01f

// packed dual-FMA: acc.(lo,hi) += a.(lo,hi) * b.(lo,hi)
#define FMA2(acc, a, b) \
    asm("fma.rn.f32x2 %0, %1, %2, %0;" : "+l"(acc) : "l"(a), "l"(b))
#define UNPACK2(lo, hi, in) \
    asm("mov.b64 {%0, %1}, %2;" : "=r"(lo), "=r"(hi) : "l"(in))

// ---------------- device scratch (static, no allocation) ----------------
__device__ float    g_fz[2 * NGRP * 2 * Hdim];   // [par][grp][b_local][H]
__device__ float    g_part[2 * NGRP * 8 * GBLK]; // [par][grp][scalar][block]
__device__ float    g_pretau[(size_t)Bb * Ss * H2];
__device__ unsigned g_bars[NGRP * 32];           // one counter per group, 128B apart

// ---------------- reset (runs every launch; graph-replay safe) ----------
__global__ void reset_kernel() {
    int i = threadIdx.x;
    if (i < NGRP * 32) g_bars[i] = 0u;
}

// ---------------- pre-tau GEMM (unchanged) -------------------------------
__global__ void pretau_gemm(const float* __restrict__ X,
                            const float* __restrict__ tw1,
                            const float* __restrict__ b1) {
    __shared__ float As[16][128];
    __shared__ float Bs[16][64];
    const int tx = threadIdx.x;
    const int row0 = blockIdx.y * 128;
    const int col0 = blockIdx.x * 64;
    const int tr = tx >> 4, tc = tx & 15;
    float acc[8][4];
#pragma unroll
    for (int i = 0; i < 8; i++)
#pragma unroll
        for (int j = 0; j < 4; j++) acc[i][j] = 0.f;

    for (int k0 = 0; k0 < Hdim; k0 += 16) {
#pragma unroll
        for (int l = 0; l < 2; l++) {
            int f = tx + l * 256;
            int r = f >> 2, c4 = (f & 3) << 2;
            float4 v = *reinterpret_cast<const float4*>(X + (size_t)(row0 + r) * Hdim + k0 + c4);
            As[c4 + 0][r] = v.x; As[c4 + 1][r] = v.y; As[c4 + 2][r] = v.z; As[c4 + 3][r] = v.w;
        }
        {
            int r = tx >> 4, c4 = (tx & 15) << 2;
            *reinterpret_cast<float4*>(&Bs[r][c4]) =
                *reinterpret_cast<const float4*>(tw1 + (size_t)(k0 + r) * H2 + col0 + c4);
        }
        __syncthreads();
#pragma unroll
        for (int k = 0; k < 16; k++) {
            float a[8], bb[4];
#pragma unroll
            for (int i = 0; i < 8; i++) a[i] = As[k][tr * 8 + i];
#pragma unroll
            for (int j = 0; j < 4; j++) bb[j] = Bs[k][tc * 4 + j];
#pragma unroll
            for (int i = 0; i < 8; i++)
#pragma unroll
                for (int j = 0; j < 4; j++) acc[i][j] += a[i] * bb[j];
        }
        __syncthreads();
    }
    float4 bv = *reinterpret_cast<const float4*>(b1 + col0 + tc * 4);
#pragma unroll
    for (int i = 0; i < 8; i++) {
        float4 o = make_float4(acc[i][0] + bv.x, acc[i][1] + bv.y,
                               acc[i][2] + bv.z, acc[i][3] + bv.w);
        *reinterpret_cast<float4*>(&g_pretau[(size_t)(row0 + tr * 8 + i) * H2 + col0 + tc * 4]) = o;
    }
}

// ---------------- conv pass: out = 0.99 * shortconv(x) (unchanged) -------
__global__ void conv_kernel(const float* __restrict__ X,
                            const float* __restrict__ cw,
                            float* __restrict__ out) {
    int idx = blockIdx.x * blockDim.x + threadIdx.x;
    if (idx >= Bb * Ss * (Hdim / 4)) return;
    int t = (idx >> 8) & (Ss - 1);
    int b = idx >> 19;
    int j = (idx & 255) << 2;
    float w[4][4];
#pragma unroll
    for (int r = 0; r < 4; r++) {
        float4 wr = *reinterpret_cast<const float4*>(cw + (j + r) * 4);
        w[r][0] = wr.x; w[r][1] = wr.y; w[r][2] = wr.z; w[r][3] = wr.w;
    }
    const float* xb = X + (size_t)b * Ss * Hdim;
    float4 acc = make_float4(0.f, 0.f, 0.f, 0.f);
#pragma unroll
    for (int k = 0; k < 4; k++) {
        int tt = t - 3 + k;
        if (tt >= 0) {
            float4 xv = *reinterpret_cast<const float4*>(xb + (size_t)tt * Hdim + j);
            acc.x += w[0][k] * xv.x; acc.y += w[1][k] * xv.y;
            acc.z += w[2][k] * xv.z; acc.w += w[3][k] * xv.w;
        }
    }
    acc.x *= (1.f - SCALEc); acc.y *= (1.f - SCALEc);
    acc.z *= (1.f - SCALEc); acc.w *= (1.f - SCALEc);
    *reinterpret_cast<float4*>(out + (size_t)idx * 4) = acc;
}

// ---------------- persistent liquid recurrence ---------------------------
// 2 independent 48-block groups. R11's proven counter barrier. Matvec uses
// packed fma.rn.f32x2 on column pairs. Sh/Shh warp-partials (red2) are
// summed lazily in the NEXT step's scalar phase (tail sync removed).
__global__ void __launch_bounds__(NT, 1)
liquid_kernel(const float* __restrict__ X,
              const float* __restrict__ Wrec,
              const float* __restrict__ tw1,
              const float* __restrict__ tw2,
              const float* __restrict__ tb2p,
              const float* __restrict__ lngp,
              const float* __restrict__ lnbp,
              float* __restrict__ out) {
    extern __shared__ float sm[];
    float* w_s  = sm;                       // 32768
    float* h_s  = w_s + RPB * Hdim;         // 2048  (2 local batches)
    float* lng  = h_s + 2 * Hdim;           // 1024
    float* lnb  = lng + Hdim;               // 1024
    float* red  = lnb + Hdim;               // 128 : [p][row0..31][b0..1]
    float* red2 = red + 128;                // 32  : [warp][b*2+{sh,shh}]
    float* xpre = red2 + 32;                // 64
    float* w2s  = xpre + 64;                // 32
    float* scal = w2s + 32;                 // 8 : a[2] oma[2] mu[2] rstd[2]

    const int tid  = threadIdx.x;
    const int warp = tid >> 5, lane = tid & 31;
    const int gid  = blockIdx.x / GBLK;      // sync group (batch pair)
    const int lblk = blockIdx.x % GBLK;      // block within group
    const int r0   = lblk * RPB;
    const bool isrec = (r0 < Hdim);
    const bool owner = isrec && ((unsigned)(tid - (r0 >> 2)) < 8u);
    const float tb2 = *tb2p;
    unsigned* barp = &g_bars[gid * 32];
    float* fzg  = g_fz + gid * (2 * Hdim);
    float* parg = g_part + gid * (8 * GBLK);

    // ---- one-time: weights / ln params / zero h / zero red2 ----
    if (isrec) {
        for (int idx = tid; idx < RPB * (Hdim / 4); idx += NT) {
            int rl = idx >> 8; int i4 = (idx & 255) << 2;
            *reinterpret_cast<float4*>(&w_s[rl * Hdim + i4]) =
                *reinterpret_cast<const float4*>(Wrec + (size_t)(r0 + rl) * Hdim + i4);
        }
    } else {
        int m0 = r0 - Hdim;
        for (int idx = tid; idx < RPB * Hdim; idx += NT) {
            int rl = idx & (RPB - 1); int i = idx >> 5;  // transpose of tau_w1 bottom half
            w_s[rl * Hdim + i] = tw1[(size_t)(Hdim + i) * H2 + m0 + rl];
        }
        if (tid < RPB) w2s[tid] = tw2[r0 - Hdim + tid];
    }
    for (int i = tid; i < Hdim; i += NT) { lng[i] = lngp[i]; lnb[i] = lnbp[i]; }
    for (int i = tid; i < 2 * Hdim / 4; i += NT)
        *reinterpret_cast<float4*>(&h_s[i * 4]) = make_float4(0.f, 0.f, 0.f, 0.f);
    if (tid < 32) red2[tid] = 0.f;
    __syncthreads();

    const int g  = warp >> 1;      // row group 0..3 (8 rows each)
    const int p  = warp & 1;       // column half
    const int rb = g * 8;

    for (int t = 0; t < Ss; t++) {
        const int par = t & 1;
        float* fz = fzg + par * (NGRP * 2 * Hdim);
        float* P  = parg + par * (NGRP * 8 * GBLK);

        // ---- prefetch x_t / pretau + conv(out) values (hidden under matvec) ----
        if (tid < 64) {
            int b = tid >> 5, rl = tid & 31;
            int gb = gid * 2 + b;
            if (isrec) xpre[tid] = X[(size_t)(gb * Ss + t) * Hdim + r0 + rl];
            else       xpre[tid] = g_pretau[(size_t)(gb * Ss + t) * H2 + (r0 - Hdim) + rl];
        }
        float4 outv[2];
        if (owner) {
#pragma unroll
            for (int b = 0; b < 2; b++)
                outv[b] = *reinterpret_cast<const float4*>(
                              &out[(size_t)((gid * 2 + b) * Ss + t) * Hdim + tid * 4]);
        }

        // ---- Phase A: matvec, packed f32x2 dual-FMA on column pairs ----
        unsigned long long av2[8][2];
#pragma unroll
        for (int r = 0; r < 8; r++) { av2[r][0] = 0ull; av2[r][1] = 0ull; }
#pragma unroll
        for (int c = 0; c < 4; c++) {
            int base = p * 512 + c * 128 + lane * 4;
            ulonglong2 h0 = *reinterpret_cast<const ulonglong2*>(&h_s[base]);
            ulonglong2 h1 = *reinterpret_cast<const ulonglong2*>(&h_s[Hdim + base]);
#pragma unroll
            for (int r = 0; r < 8; r++) {
                ulonglong2 wv = *reinterpret_cast<const ulonglong2*>(&w_s[(rb + r) * Hdim + base]);
                FMA2(av2[r][0], wv.x, h0.x);
                FMA2(av2[r][0], wv.y, h0.y);
                FMA2(av2[r][1], wv.x, h1.x);
                FMA2(av2[r][1], wv.y, h1.y);
            }
        }
#pragma unroll
        for (int r = 0; r < 8; r++)
#pragma unroll
            for (int b = 0; b < 2; b++) {
                unsigned lo, hi;
                UNPACK2(lo, hi, av2[r][b]);
                float v = __uint_as_float(lo) + __uint_as_float(hi);
#pragma unroll
                for (int off = 16; off > 0; off >>= 1) v += __shfl_down_sync(0xffffffffu, v, off);
                if (lane == 0) red[p * 64 + (rb + r) * 2 + b] = v;
            }
        __syncthreads();

        // ---- f/z + per-block scalar partial stores (warp = batch) ----
        if (tid < 64) {
            int b = warp, rl = lane;
            float d = red[rl * 2 + b] + red[64 + rl * 2 + b];
            if (isrec) {
                float f = tanhf(xpre[tid] + d);
                fz[b * Hdim + r0 + rl] = f;
                float hv = h_s[b * Hdim + r0 + rl];
                float pf = f, pff = f * f, phf = hv * f;
#pragma unroll
                for (int off = 16; off > 0; off >>= 1) {
                    pf  += __shfl_down_sync(0xffffffffu, pf,  off);
                    pff += __shfl_down_sync(0xffffffffu, pff, off);
                    phf += __shfl_down_sync(0xffffffffu, phf, off);
                }
                if (rl == 0) {
                    P[(b * 4 + 1) * GBLK + lblk] = pf;
                    P[(b * 4 + 2) * GBLK + lblk] = pff;
                    P[(b * 4 + 3) * GBLK + lblk] = phf;
                }
            } else {
                float z = tanhf(xpre[tid] + d);
                float pz = z * w2s[rl];
#pragma unroll
                for (int off = 16; off > 0; off >>= 1)
                    pz += __shfl_down_sync(0xffffffffu, pz, off);
                if (rl == 0) P[(b * 4 + 0) * GBLK + lblk] = pz;
            }
        }
        __syncthreads();   // CTA-scope happens-before for all STGs above

        // ---- group barrier: release arrive + single acquire poller (R11) ----
        if (tid == 0) {
            unsigned dummy;
            asm volatile("atom.add.release.gpu.global.u32 %0, [%1], 1;"
                         : "=r"(dummy) : "l"(barp) : "memory");
            unsigned target = (unsigned)(t + 1) * GBLK, v;
            do { asm volatile("ld.acquire.gpu.u32 %0, [%1];" : "=r"(v) : "l"(barp) : "memory"); }
            while (v < target);
        }
        __syncthreads();

        // ---- Phase B: prefetch f into registers FIRST ----
        float4 f4r[2];
#pragma unroll
        for (int b = 0; b < 2; b++)
            f4r[b] = __ldcg(reinterpret_cast<const float4*>(&fz[b * Hdim + tid * 4]));

        // ---- cross-block scalar reduction: warp b handles batch b.
        //      red2 warp-partials from the PREVIOUS step are summed here
        //      (hidden under the L2 load latency). ----
        if (warp < 2) {
            const int b = warp;
            float z   = (lane < GBLK - 32)
                          ? __ldcg(&P[(b * 4 + 0) * GBLK + 32 + lane]) : 0.f;   // 16 tau blocks
            float sf  = __ldcg(&P[(b * 4 + 1) * GBLK + lane]);                  // 32 rec blocks
            float sff = __ldcg(&P[(b * 4 + 2) * GBLK + lane]);
            float shf = __ldcg(&P[(b * 4 + 3) * GBLK + lane]);
            float sh = 0.f, shh = 0.f;
            if (lane == 0) {
#pragma unroll
                for (int w = 0; w < 8; w++) {
                    sh  += red2[w * 4 + b * 2];
                    shh += red2[w * 4 + b * 2 + 1];
                }
            }
#pragma unroll
            for (int off = 16; off > 0; off >>= 1) {
                z   += __shfl_down_sync(0xffffffffu, z,   off);
                sf  += __shfl_down_sync(0xffffffffu, sf,  off);
                sff += __shfl_down_sync(0xffffffffu, sff, off);
                shf += __shfl_down_sync(0xffffffffu, shf, off);
            }
            if (lane == 0) {
                float sig = 1.f / (1.f + expf(-(z + tb2)));
                float tau = 1.f + 4.f * sig;
                float a = DTc / tau, oma = 1.f - a;
                float mu  = (oma * sh + a * sf) * (1.f / (float)Hdim);
                float sy2 = oma * oma * shh + 2.f * a * oma * shf + a * a * sff;
                float var = sy2 * (1.f / (float)Hdim) - mu * mu;
                scal[b] = a; scal[2 + b] = oma; scal[4 + b] = mu;
                scal[6 + b] = rsqrtf(var + 1e-5f);
            }
        }
        __syncthreads();

        // ---- local h update (2 batches) + fused out write + Sh/Shh partials ----
        {
            const int j4 = tid * 4;
            float4 g4 = *reinterpret_cast<const float4*>(&lng[j4]);
            float4 b4 = *reinterpret_cast<const float4*>(&lnb[j4]);
            float psh[2], pshh[2];
#pragma unroll
            for (int b = 0; b < 2; b++) {
                float a = scal[b], oma = scal[2 + b], mu = scal[4 + b], rs = scal[6 + b];
                float4 f4 = f4r[b];
                float4 h4 = *reinterpret_cast<const float4*>(&h_s[b * Hdim + j4]);
                float4 hn;
                hn.x = (oma * h4.x + a * f4.x - mu) * rs * g4.x + b4.x;
                hn.y = (oma * h4.y + a * f4.y - mu) * rs * g4.y + b4.y;
                hn.z = (oma * h4.z + a * f4.z - mu) * rs * g4.z + b4.z;
                hn.w = (oma * h4.w + a * f4.w - mu) * rs * g4.w + b4.w;
                *reinterpret_cast<float4*>(&h_s[b * Hdim + j4]) = hn;
                if (owner) {
                    float4 o4;
                    o4.x = outv[b].x + SCALEc * hn.x;
                    o4.y = outv[b].y + SCALEc * hn.y;
                    o4.z = outv[b].z + SCALEc * hn.z;
                    o4.w = outv[b].w + SCALEc * hn.w;
                    *reinterpret_cast<float4*>(
                        &out[(size_t)((gid * 2 + b) * Ss + t) * Hdim + j4]) = o4;
                }
                psh[b]  = hn.x + hn.y + hn.z + hn.w;
                pshh[b] = hn.x * hn.x + hn.y * hn.y + hn.z * hn.z + hn.w * hn.w;
            }
#pragma unroll
            for (int b = 0; b < 2; b++) {
                float v1 = psh[b], v2 = pshh[b];
#pragma unroll
                for (int off = 16; off > 0; off >>= 1) {
                    v1 += __shfl_down_sync(0xffffffffu, v1, off);
                    v2 += __shfl_down_sync(0xffffffffu, v2, off);
                }
                if (lane == 0) { red2[warp * 4 + b * 2] = v1; red2[warp * 4 + b * 2 + 1] = v2; }
            }
        }
        // no tail sync / no final summation: red2 partials are consumed in the
        // NEXT step's scalar phase; the next pre-barrier __syncthreads orders
        // these stores before that step's barrier arrival.
    }
}

// ---------------- launch --------------------------------------------------
extern "C" void kernel_launch(void* const* d_in, const int* in_sizes, int n_in,
                              void* d_out, int out_size) {
    const float* X   = (const float*)d_in[0];
    const float* cw  = (const float*)d_in[1];
    const float* Wr  = (const float*)d_in[2];
    const float* tw1 = (const float*)d_in[3];
    const float* tb1 = (const float*)d_in[4];
    const float* tw2 = (const float*)d_in[5];
    const float* tb2 = (const float*)d_in[6];
    const float* lg  = (const float*)d_in[7];
    const float* lb  = (const float*)d_in[8];
    float* out = (float*)d_out;

    const int smem_bytes = (RPB * Hdim + 2 * Hdim + Hdim + Hdim +
                            128 + 32 + 64 + 32 + 8) * 4;
    cudaFuncSetAttribute(liquid_kernel, cudaFuncAttributeMaxDynamicSharedMemorySize, smem_bytes);

    reset_kernel<<<1, 64>>>();

    dim3 ggrid(H2 / 64, (Bb * Ss) / 128);
    pretau_gemm<<<ggrid, 256>>>(X, tw1, tb1);

    conv_kernel<<<(Bb * Ss * (Hdim / 4)) / 256, 256>>>(X, cw, out);

    liquid_kernel<<<NBLK, NT, smem_bytes>>>(X, Wr, tw1, tw2, tb2, lg, lb, out);
}

// round 17
// speedup vs baseline: 1.2962x; 1.1181x over previous
#include <cuda_runtime.h>

#define Hdim 1024
#define H2   512
#define Bb   4
#define Ss   2048
#define NGRP 2       // independent sync groups (2 batches each)
#define GBLK 48      // blocks per group (32 rec + 16 tau)
#define NBLK (NGRP * GBLK)
#define RPB  32      // weight rows per block (held in REGISTERS)
#define NT   256     // 8 warps
#define DTc  0.1f
#define SCALEc 0.01f

// packed dual-FMA: acc.(lo,hi) += a.(lo,hi) * b.(lo,hi)
#define FMA2(acc, a, b) \
    asm("fma.rn.f32x2 %0, %1, %2, %0;" : "+l"(acc) : "l"(a), "l"(b))
#define UNPACK2(lo, hi, in) \
    asm("mov.b64 {%0, %1}, %2;" : "=r"(lo), "=r"(hi) : "l"(in))

// ---------------- device scratch (static, no allocation) ----------------
__device__ float    g_fz[2 * NGRP * 2 * Hdim];   // [par][grp][b_local][H]
__device__ float    g_part[2 * NGRP * 8 * GBLK]; // [par][grp][scalar][block]
__device__ float    g_pretau[(size_t)Bb * Ss * H2];
__device__ unsigned g_bars[NGRP * 32];           // one counter per group, 128B apart

// ---------------- reset (runs every launch; graph-replay safe) ----------
__global__ void reset_kernel() {
    int i = threadIdx.x;
    if (i < NGRP * 32) g_bars[i] = 0u;
}

// ---------------- pre-tau GEMM (unchanged) -------------------------------
__global__ void pretau_gemm(const float* __restrict__ X,
                            const float* __restrict__ tw1,
                            const float* __restrict__ b1) {
    __shared__ float As[16][128];
    __shared__ float Bs[16][64];
    const int tx = threadIdx.x;
    const int row0 = blockIdx.y * 128;
    const int col0 = blockIdx.x * 64;
    const int tr = tx >> 4, tc = tx & 15;
    float acc[8][4];
#pragma unroll
    for (int i = 0; i < 8; i++)
#pragma unroll
        for (int j = 0; j < 4; j++) acc[i][j] = 0.f;

    for (int k0 = 0; k0 < Hdim; k0 += 16) {
#pragma unroll
        for (int l = 0; l < 2; l++) {
            int f = tx + l * 256;
            int r = f >> 2, c4 = (f & 3) << 2;
            float4 v = *reinterpret_cast<const float4*>(X + (size_t)(row0 + r) * Hdim + k0 + c4);
            As[c4 + 0][r] = v.x; As[c4 + 1][r] = v.y; As[c4 + 2][r] = v.z; As[c4 + 3][r] = v.w;
        }
        {
            int r = tx >> 4, c4 = (tx & 15) << 2;
            *reinterpret_cast<float4*>(&Bs[r][c4]) =
                *reinterpret_cast<const float4*>(tw1 + (size_t)(k0 + r) * H2 + col0 + c4);
        }
        __syncthreads();
#pragma unroll
        for (int k = 0; k < 16; k++) {
            float a[8], bb[4];
#pragma unroll
            for (int i = 0; i < 8; i++) a[i] = As[k][tr * 8 + i];
#pragma unroll
            for (int j = 0; j < 4; j++) bb[j] = Bs[k][tc * 4 + j];
#pragma unroll
            for (int i = 0; i < 8; i++)
#pragma unroll
                for (int j = 0; j < 4; j++) acc[i][j] += a[i] * bb[j];
        }
        __syncthreads();
    }
    float4 bv = *reinterpret_cast<const float4*>(b1 + col0 + tc * 4);
#pragma unroll
    for (int i = 0; i < 8; i++) {
        float4 o = make_float4(acc[i][0] + bv.x, acc[i][1] + bv.y,
                               acc[i][2] + bv.z, acc[i][3] + bv.w);
        *reinterpret_cast<float4*>(&g_pretau[(size_t)(row0 + tr * 8 + i) * H2 + col0 + tc * 4]) = o;
    }
}

// ---------------- conv pass: out = 0.99 * shortconv(x) (unchanged) -------
__global__ void conv_kernel(const float* __restrict__ X,
                            const float* __restrict__ cw,
                            float* __restrict__ out) {
    int idx = blockIdx.x * blockDim.x + threadIdx.x;
    if (idx >= Bb * Ss * (Hdim / 4)) return;
    int t = (idx >> 8) & (Ss - 1);
    int b = idx >> 19;
    int j = (idx & 255) << 2;
    float w[4][4];
#pragma unroll
    for (int r = 0; r < 4; r++) {
        float4 wr = *reinterpret_cast<const float4*>(cw + (j + r) * 4);
        w[r][0] = wr.x; w[r][1] = wr.y; w[r][2] = wr.z; w[r][3] = wr.w;
    }
    const float* xb = X + (size_t)b * Ss * Hdim;
    float4 acc = make_float4(0.f, 0.f, 0.f, 0.f);
#pragma unroll
    for (int k = 0; k < 4; k++) {
        int tt = t - 3 + k;
        if (tt >= 0) {
            float4 xv = *reinterpret_cast<const float4*>(xb + (size_t)tt * Hdim + j);
            acc.x += w[0][k] * xv.x; acc.y += w[1][k] * xv.y;
            acc.z += w[2][k] * xv.z; acc.w += w[3][k] * xv.w;
        }
    }
    acc.x *= (1.f - SCALEc); acc.y *= (1.f - SCALEc);
    acc.z *= (1.f - SCALEc); acc.w *= (1.f - SCALEc);
    *reinterpret_cast<float4*>(out + (size_t)idx * 4) = acc;
}

// ---------------- persistent liquid recurrence ---------------------------
// 2 independent 48-block groups. Weights live in REGISTERS (64 ulonglong2
// per thread, loaded once). Matvec: warp = 4 full rows x 2 batches; h
// streams from SMEM (broadcast), FMA2 from registers. R11 counter barrier.
__global__ void __launch_bounds__(NT, 1)
liquid_kernel(const float* __restrict__ X,
              const float* __restrict__ Wrec,
              const float* __restrict__ tw1,
              const float* __restrict__ tw2,
              const float* __restrict__ tb2p,
              const float* __restrict__ lngp,
              const float* __restrict__ lnbp,
              float* __restrict__ out) {
    extern __shared__ float sm[];
    float* h_s  = sm;                       // 2048  (2 local batches)
    float* lng  = h_s + 2 * Hdim;           // 1024
    float* lnb  = lng + Hdim;               // 1024
    float* red  = lnb + Hdim;               // 64 : [row0..31][b0..1]
    float* red2 = red + 64;                 // 32 : [warp][b*2+{sh,shh}]
    float* xpre = red2 + 32;                // 64
    float* w2s  = xpre + 64;                // 32
    float* scal = w2s + 32;                 // 8 : a[2] oma[2] mu[2] rstd[2]

    const int tid  = threadIdx.x;
    const int warp = tid >> 5, lane = tid & 31;
    const int gid  = blockIdx.x / GBLK;      // sync group (batch pair)
    const int lblk = blockIdx.x % GBLK;      // block within group
    const int r0   = lblk * RPB;
    const bool isrec = (r0 < Hdim);
    const bool owner = isrec && ((unsigned)(tid - (r0 >> 2)) < 8u);
    const float tb2 = *tb2p;
    unsigned* barp = &g_bars[gid * 32];
    float* fzg  = g_fz + gid * (2 * Hdim);
    float* parg = g_part + gid * (8 * GBLK);

    // ---- one-time: weights -> REGISTERS (4 rows x 8 chunks of 2 pairs) ----
    // wreg[r][k] covers row (r0 + 4*warp + r), cols k*128 + lane*4 .. +3
    ulonglong2 wreg[4][8];
    if (isrec) {
#pragma unroll
        for (int r = 0; r < 4; r++)
#pragma unroll
            for (int k = 0; k < 8; k++)
                wreg[r][k] = *reinterpret_cast<const ulonglong2*>(
                    Wrec + (size_t)(r0 + warp * 4 + r) * Hdim + k * 128 + lane * 4);
    } else {
        int m0 = r0 - Hdim;
#pragma unroll
        for (int r = 0; r < 4; r++)
#pragma unroll
            for (int k = 0; k < 8; k++) {
                union { float4 f; ulonglong2 u; } tmp;
                int j0 = k * 128 + lane * 4;
                tmp.f.x = tw1[(size_t)(Hdim + j0 + 0) * H2 + m0 + warp * 4 + r];
                tmp.f.y = tw1[(size_t)(Hdim + j0 + 1) * H2 + m0 + warp * 4 + r];
                tmp.f.z = tw1[(size_t)(Hdim + j0 + 2) * H2 + m0 + warp * 4 + r];
                tmp.f.w = tw1[(size_t)(Hdim + j0 + 3) * H2 + m0 + warp * 4 + r];
                wreg[r][k] = tmp.u;
            }
        if (tid < RPB) w2s[tid] = tw2[r0 - Hdim + tid];
    }
    for (int i = tid; i < Hdim; i += NT) { lng[i] = lngp[i]; lnb[i] = lnbp[i]; }
    for (int i = tid; i < 2 * Hdim / 4; i += NT)
        *reinterpret_cast<float4*>(&h_s[i * 4]) = make_float4(0.f, 0.f, 0.f, 0.f);
    if (tid < 32) red2[tid] = 0.f;
    __syncthreads();

    for (int t = 0; t < Ss; t++) {
        const int par = t & 1;
        float* fz = fzg + par * (NGRP * 2 * Hdim);
        float* P  = parg + par * (NGRP * 8 * GBLK);

        // ---- prefetch x_t / pretau + conv(out) values (hidden under matvec) ----
        if (tid < 64) {
            int b = tid >> 5, rl = tid & 31;
            int gb = gid * 2 + b;
            if (isrec) xpre[tid] = X[(size_t)(gb * Ss + t) * Hdim + r0 + rl];
            else       xpre[tid] = g_pretau[(size_t)(gb * Ss + t) * H2 + (r0 - Hdim) + rl];
        }
        float4 outv[2];
        if (owner) {
#pragma unroll
            for (int b = 0; b < 2; b++)
                outv[b] = *reinterpret_cast<const float4*>(
                              &out[(size_t)((gid * 2 + b) * Ss + t) * Hdim + tid * 4]);
        }

        // ---- Phase A: matvec from REGISTER weights, h broadcast from SMEM ----
        unsigned long long acc[4][2];
#pragma unroll
        for (int r = 0; r < 4; r++) { acc[r][0] = 0ull; acc[r][1] = 0ull; }
#pragma unroll
        for (int k = 0; k < 8; k++) {
            int base = k * 128 + lane * 4;
            ulonglong2 h0 = *reinterpret_cast<const ulonglong2*>(&h_s[base]);
            ulonglong2 h1 = *reinterpret_cast<const ulonglong2*>(&h_s[Hdim + base]);
#pragma unroll
            for (int r = 0; r < 4; r++) {
                FMA2(acc[r][0], wreg[r][k].x, h0.x);
                FMA2(acc[r][0], wreg[r][k].y, h0.y);
                FMA2(acc[r][1], wreg[r][k].x, h1.x);
                FMA2(acc[r][1], wreg[r][k].y, h1.y);
            }
        }
#pragma unroll
        for (int r = 0; r < 4; r++)
#pragma unroll
            for (int b = 0; b < 2; b++) {
                unsigned lo, hi;
                UNPACK2(lo, hi, acc[r][b]);
                float v = __uint_as_float(lo) + __uint_as_float(hi);
#pragma unroll
                for (int off = 16; off > 0; off >>= 1) v += __shfl_down_sync(0xffffffffu, v, off);
                if (lane == 0) red[(warp * 4 + r) * 2 + b] = v;
            }
        __syncthreads();

        // ---- f/z + per-block scalar partial stores (warp = batch) ----
        if (tid < 64) {
            int b = warp, rl = lane;
            float d = red[rl * 2 + b];
            if (isrec) {
                float f = tanhf(xpre[tid] + d);
                fz[b * Hdim + r0 + rl] = f;
                float hv = h_s[b * Hdim + r0 + rl];
                float pf = f, pff = f * f, phf = hv * f;
#pragma unroll
                for (int off = 16; off > 0; off >>= 1) {
                    pf  += __shfl_down_sync(0xffffffffu, pf,  off);
                    pff += __shfl_down_sync(0xffffffffu, pff, off);
                    phf += __shfl_down_sync(0xffffffffu, phf, off);
                }
                if (rl == 0) {
                    P[(b * 4 + 1) * GBLK + lblk] = pf;
                    P[(b * 4 + 2) * GBLK + lblk] = pff;
                    P[(b * 4 + 3) * GBLK + lblk] = phf;
                }
            } else {
                float z = tanhf(xpre[tid] + d);
                float pz = z * w2s[rl];
#pragma unroll
                for (int off = 16; off > 0; off >>= 1)
                    pz += __shfl_down_sync(0xffffffffu, pz, off);
                if (rl == 0) P[(b * 4 + 0) * GBLK + lblk] = pz;
            }
        }
        __syncthreads();   // CTA-scope happens-before for all STGs above

        // ---- group barrier: release arrive + single acquire poller (R11) ----
        if (tid == 0) {
            unsigned dummy;
            asm volatile("atom.add.release.gpu.global.u32 %0, [%1], 1;"
                         : "=r"(dummy) : "l"(barp) : "memory");
            unsigned target = (unsigned)(t + 1) * GBLK, v;
            do { asm volatile("ld.acquire.gpu.u32 %0, [%1];" : "=r"(v) : "l"(barp) : "memory"); }
            while (v < target);
        }
        __syncthreads();

        // ---- Phase B: prefetch f into registers FIRST ----
        float4 f4r[2];
#pragma unroll
        for (int b = 0; b < 2; b++)
            f4r[b] = __ldcg(reinterpret_cast<const float4*>(&fz[b * Hdim + tid * 4]));

        // ---- cross-block scalar reduction: warp b handles batch b.
        //      red2 warp-partials from the PREVIOUS step summed here. ----
        if (warp < 2) {
            const int b = warp;
            float z   = (lane < GBLK - 32)
                          ? __ldcg(&P[(b * 4 + 0) * GBLK + 32 + lane]) : 0.f;   // 16 tau blocks
            float sf  = __ldcg(&P[(b * 4 + 1) * GBLK + lane]);                  // 32 rec blocks
            float sff = __ldcg(&P[(b * 4 + 2) * GBLK + lane]);
            float shf = __ldcg(&P[(b * 4 + 3) * GBLK + lane]);
            float sh = 0.f, shh = 0.f;
            if (lane == 0) {
#pragma unroll
                for (int w = 0; w < 8; w++) {
                    sh  += red2[w * 4 + b * 2];
                    shh += red2[w * 4 + b * 2 + 1];
                }
            }
#pragma unroll
            for (int off = 16; off > 0; off >>= 1) {
                z   += __shfl_down_sync(0xffffffffu, z,   off);
                sf  += __shfl_down_sync(0xffffffffu, sf,  off);
                sff += __shfl_down_sync(0xffffffffu, sff, off);
                shf += __shfl_down_sync(0xffffffffu, shf, off);
            }
            if (lane == 0) {
                float sig = 1.f / (1.f + expf(-(z + tb2)));
                float tau = 1.f + 4.f * sig;
                float a = DTc / tau, oma = 1.f - a;
                float mu  = (oma * sh + a * sf) * (1.f / (float)Hdim);
                float sy2 = oma * oma * shh + 2.f * a * oma * shf + a * a * sff;
                float var = sy2 * (1.f / (float)Hdim) - mu * mu;
                scal[b] = a; scal[2 + b] = oma; scal[4 + b] = mu;
                scal[6 + b] = rsqrtf(var + 1e-5f);
            }
        }
        __syncthreads();

        // ---- local h update (2 batches) + fused out write + Sh/Shh partials ----
        {
            const int j4 = tid * 4;
            float4 g4 = *reinterpret_cast<const float4*>(&lng[j4]);
            float4 b4 = *reinterpret_cast<const float4*>(&lnb[j4]);
            float psh[2], pshh[2];
#pragma unroll
            for (int b = 0; b < 2; b++) {
                float a = scal[b], oma = scal[2 + b], mu = scal[4 + b], rs = scal[6 + b];
                float4 f4 = f4r[b];
                float4 h4 = *reinterpret_cast<const float4*>(&h_s[b * Hdim + j4]);
                float4 hn;
                hn.x = (oma * h4.x + a * f4.x - mu) * rs * g4.x + b4.x;
                hn.y = (oma * h4.y + a * f4.y - mu) * rs * g4.y + b4.y;
                hn.z = (oma * h4.z + a * f4.z - mu) * rs * g4.z + b4.z;
                hn.w = (oma * h4.w + a * f4.w - mu) * rs * g4.w + b4.w;
                *reinterpret_cast<float4*>(&h_s[b * Hdim + j4]) = hn;
                if (owner) {
                    float4 o4;
                    o4.x = outv[b].x + SCALEc * hn.x;
                    o4.y = outv[b].y + SCALEc * hn.y;
                    o4.z = outv[b].z + SCALEc * hn.z;
                    o4.w = outv[b].w + SCALEc * hn.w;
                    *reinterpret_cast<float4*>(
                        &out[(size_t)((gid * 2 + b) * Ss + t) * Hdim + j4]) = o4;
                }
                psh[b]  = hn.x + hn.y + hn.z + hn.w;
                pshh[b] = hn.x * hn.x + hn.y * hn.y + hn.z * hn.z + hn.w * hn.w;
            }
#pragma unroll
            for (int b = 0; b < 2; b++) {
                float v1 = psh[b], v2 = pshh[b];
#pragma unroll
                for (int off = 16; off > 0; off >>= 1) {
                    v1 += __shfl_down_sync(0xffffffffu, v1, off);
                    v2 += __shfl_down_sync(0xffffffffu, v2, off);
                }
                if (lane == 0) { red2[warp * 4 + b * 2] = v1; red2[warp * 4 + b * 2 + 1] = v2; }
            }
        }
        // tail sync: orders this step's h_s stores before next step's matvec
        // reads from OTHER warps.
        __syncthreads();
    }
}

// ---------------- launch --------------------------------------------------
extern "C" void kernel_launch(void* const* d_in, const int* in_sizes, int n_in,
                              void* d_out, int out_size) {
    const float* X   = (const float*)d_in[0];
    const float* cw  = (const float*)d_in[1];
    const float* Wr  = (const float*)d_in[2];
    const float* tw1 = (const float*)d_in[3];
    const float* tb1 = (const float*)d_in[4];
    const float* tw2 = (const float*)d_in[5];
    const float* tb2 = (const float*)d_in[6];
    const float* lg  = (const float*)d_in[7];
    const float* lb  = (const float*)d_in[8];
    float* out = (float*)d_out;

    const int smem_bytes = (2 * Hdim + Hdim + Hdim + 64 + 32 + 64 + 32 + 8) * 4;
    cudaFuncSetAttribute(liquid_kernel, cudaFuncAttributeMaxDynamicSharedMemorySize, smem_bytes);

    reset_kernel<<<1, 64>>>();

    dim3 ggrid(H2 / 64, (Bb * Ss) / 128);
    pretau_gemm<<<ggrid, 256>>>(X, tw1, tb1);

    conv_kernel<<<(Bb * Ss * (Hdim / 4)) / 256, 256>>>(X, cw, out);

    liquid_kernel<<<NBLK, NT, smem_bytes>>>(X, Wr, tw1, tw2, tb2, lg, lb, out);
}